// round 1
// baseline (speedup 1.0000x reference)
#include <cuda_runtime.h>
#include <math.h>

#define N    8192
#define FIN  256
#define FOUT 128

#define MT   64     // rows per block in attention kernel
#define KT   32     // j-chunk
#define WPAD 68     // padded row stride for w tile (bank-conflict relief, 16B aligned)

// ---- scratch (device globals; no allocation allowed) ----
__device__ float g_Wh[(size_t)N * FOUT];   // 4 MB
__device__ float g_s1[N], g_s2[N];
__device__ float g_R1p[N], g_R1n[N], g_E2p[N], g_E2n[N];
__device__ float g_S1M, g_S2M;

// ============================================================
// Kernel 1: Wh = h @ W^T   (h:[N,FIN], W:[FOUT,FIN] both k-major)
// block = 128 threads (one per output column f), 32 rows per block
// ============================================================
__global__ void __launch_bounds__(128) k_wh(const float* __restrict__ h,
                                            const float* __restrict__ W) {
    __shared__ float hs[32][FIN];
    const int row0 = blockIdx.x * 32;
    const int t = threadIdx.x;

    // load 32x256 h tile (coalesced float4)
    const float4* h4 = (const float4*)(h + (size_t)row0 * FIN);
    float4* hs4 = (float4*)&hs[0][0];
    #pragma unroll
    for (int u = 0; u < 16; u++) hs4[t + u * 128] = h4[t + u * 128];
    __syncthreads();

    const int f = t;
    const float4* W4 = (const float4*)(W + (size_t)f * FIN);

    float acc[32];
    #pragma unroll
    for (int r = 0; r < 32; r++) acc[r] = 0.f;

    for (int k0 = 0; k0 < FIN; k0 += 32) {
        float4 wv[8];
        #pragma unroll
        for (int c = 0; c < 8; c++) wv[c] = W4[k0 / 4 + c];
        #pragma unroll
        for (int r = 0; r < 32; r++) {
            const float4* hv4 = (const float4*)&hs[r][k0];
            #pragma unroll
            for (int c = 0; c < 8; c++) {
                float4 hv = hv4[c];
                acc[r] += hv.x * wv[c].x;
                acc[r] += hv.y * wv[c].y;
                acc[r] += hv.z * wv[c].z;
                acc[r] += hv.w * wv[c].w;
            }
        }
    }
    #pragma unroll
    for (int r = 0; r < 32; r++)
        g_Wh[(size_t)(row0 + r) * FOUT + f] = acc[r];
}

// ============================================================
// Kernel 2: s1 = Wh@a1, s2 = Wh@a2   (warp per row)
// ============================================================
__global__ void __launch_bounds__(256) k_s12(const float* __restrict__ a1,
                                             const float* __restrict__ a2) {
    const int gwarp = (blockIdx.x * 256 + threadIdx.x) >> 5;
    const int lane = threadIdx.x & 31;
    if (gwarp >= N) return;
    const float* whr = g_Wh + (size_t)gwarp * FOUT;
    float p1 = 0.f, p2 = 0.f;
    #pragma unroll
    for (int c = 0; c < 4; c++) {
        float v = whr[lane + 32 * c];
        p1 += v * __ldg(&a1[lane + 32 * c]);
        p2 += v * __ldg(&a2[lane + 32 * c]);
    }
    #pragma unroll
    for (int o = 16; o > 0; o >>= 1) {
        p1 += __shfl_xor_sync(0xffffffffu, p1, o);
        p2 += __shfl_xor_sync(0xffffffffu, p2, o);
    }
    if (lane == 0) { g_s1[gwarp] = p1; g_s2[gwarp] = p2; }
}

// ============================================================
// Kernel 2b: global maxima of s1, s2 (single block)
// ============================================================
__global__ void __launch_bounds__(256) k_max() {
    __shared__ float sm1[256], sm2[256];
    const int t = threadIdx.x;
    float m1 = -1e30f, m2 = -1e30f;
    for (int i = t; i < N; i += 256) {
        m1 = fmaxf(m1, g_s1[i]);
        m2 = fmaxf(m2, g_s2[i]);
    }
    sm1[t] = m1; sm2[t] = m2;
    __syncthreads();
    for (int s = 128; s > 0; s >>= 1) {
        if (t < s) {
            sm1[t] = fmaxf(sm1[t], sm1[t + s]);
            sm2[t] = fmaxf(sm2[t], sm2[t + s]);
        }
        __syncthreads();
    }
    if (t == 0) { g_S1M = sm1[0]; g_S2M = sm2[0]; }
}

// ============================================================
// Kernel 2c: factorized exp weights
//  exp(lrelu(s1+s2) - C1 - C2) = R1p[i]*E2p[j]  (s1+s2>=0)
//                              = R1n[i]*E2n[j]  (s1+s2< 0)
// ============================================================
__global__ void __launch_bounds__(256) k_factors() {
    const int i = blockIdx.x * 256 + threadIdx.x;
    if (i >= N) return;
    const float C1 = g_S1M, C2 = g_S2M;
    const float s1 = g_s1[i], s2 = g_s2[i];
    g_R1p[i] = expf(s1 - C1);
    g_R1n[i] = expf(0.2f * s1 - C1);
    g_E2p[i] = expf(s2 - C2);
    g_E2n[i] = expf(0.2f * s2 - C2);
}

// ============================================================
// Kernel 3: fused masked-softmax attention GEMM + ELU epilogue
//  out[i,f] = elu( (sum_j w_ij * Wh[j,f]) / (sum_j w_ij) )
//  w_ij = adj_ij>0 ? (s1_i+s2_j>=0 ? R1p_i*E2p_j : R1n_i*E2n_j) : 0
// grid = N/MT blocks, 256 threads, 8x4 register tile, prefetch pipeline
// ============================================================
__global__ void __launch_bounds__(256) k_attn(const int* __restrict__ adj,
                                              float* __restrict__ out) {
    __shared__ float w_s[KT][WPAD];     // w tile, transposed [k][m]
    __shared__ float wh_s[KT][FOUT];    // Wh tile [k][f]
    __shared__ float z_s[MT];

    const int t = threadIdx.x;
    const int row0 = blockIdx.x * MT;

    // generation-phase mapping: row m = t/4, 8 j's per thread (jg = t&3)
    const int m  = t >> 2;
    const int jg = t & 3;
    const float s1m  = g_s1[row0 + m];
    const float r1pm = g_R1p[row0 + m];
    const float r1nm = g_R1n[row0 + m];
    const size_t arow = (size_t)(row0 + m) * N;

    // FMA-phase mapping: 8 rows x 4 cols per thread
    const int cg = t & 31, rg = t >> 5;
    const int f0 = cg * 4, r0 = rg * 8;

    float acc[8][4];
    #pragma unroll
    for (int i = 0; i < 8; i++)
        #pragma unroll
        for (int j = 0; j < 4; j++) acc[i][j] = 0.f;
    float zpart = 0.f;

    // prefetch registers
    int4 aj0, aj1;
    float4 s2a, s2b, epa, epb, ena, enb;
    float4 whv[4];

    auto load_stage = [&](int j0) {
        const int jb = j0 + jg * 8;
        const int* ap = adj + arow + jb;
        aj0 = *(const int4*)ap;
        aj1 = *(const int4*)(ap + 4);
        s2a = *(const float4*)(g_s2 + jb);  s2b = *(const float4*)(g_s2 + jb + 4);
        epa = *(const float4*)(g_E2p + jb); epb = *(const float4*)(g_E2p + jb + 4);
        ena = *(const float4*)(g_E2n + jb); enb = *(const float4*)(g_E2n + jb + 4);
        #pragma unroll
        for (int u = 0; u < 4; u++) {
            const int idx = t + u * 256;
            const int kk = idx >> 5, fq = idx & 31;
            whv[u] = *(const float4*)(g_Wh + (size_t)(j0 + kk) * FOUT + fq * 4);
        }
    };

    load_stage(0);

    for (int j0 = 0; j0 < N; j0 += KT) {
        __syncthreads();   // previous FMA phase done reading smem

        // commit Wh tile
        #pragma unroll
        for (int u = 0; u < 4; u++) {
            const int idx = t + u * 256;
            const int kk = idx >> 5, fq = idx & 31;
            *(float4*)&wh_s[kk][fq * 4] = whv[u];
        }
        // compute + commit w tile, accumulate partial Z
        {
            float w;
            #define DOW(q, A, S, EP, EN)                                        \
                w = 0.f;                                                        \
                if ((A) > 0) w = (s1m + (S) >= 0.f) ? r1pm * (EP) : r1nm * (EN);\
                w_s[jg * 8 + (q)][m] = w;                                       \
                zpart += w;
            DOW(0, aj0.x, s2a.x, epa.x, ena.x)
            DOW(1, aj0.y, s2a.y, epa.y, ena.y)
            DOW(2, aj0.z, s2a.z, epa.z, ena.z)
            DOW(3, aj0.w, s2a.w, epa.w, ena.w)
            DOW(4, aj1.x, s2b.x, epb.x, enb.x)
            DOW(5, aj1.y, s2b.y, epb.y, enb.y)
            DOW(6, aj1.z, s2b.z, epb.z, enb.z)
            DOW(7, aj1.w, s2b.w, epb.w, enb.w)
            #undef DOW
        }
        // prefetch next chunk (overlaps with FMA phase)
        const int jn = j0 + KT;
        if (jn < N) load_stage(jn);

        __syncthreads();

        // FMA phase: 32 k-steps, 8x4 per thread
        #pragma unroll
        for (int kk = 0; kk < KT; kk++) {
            const float4 wa = *(const float4*)&w_s[kk][r0];       // broadcast
            const float4 wb = *(const float4*)&w_s[kk][r0 + 4];   // broadcast
            const float4 bv = *(const float4*)&wh_s[kk][f0];
            const float wr[8] = {wa.x, wa.y, wa.z, wa.w, wb.x, wb.y, wb.z, wb.w};
            const float bb[4] = {bv.x, bv.y, bv.z, bv.w};
            #pragma unroll
            for (int rr = 0; rr < 8; rr++)
                #pragma unroll
                for (int cc = 0; cc < 4; cc++)
                    acc[rr][cc] += wr[rr] * bb[cc];
        }
    }

    // reduce Z across the 4 threads sharing a row (lane bits 0,1)
    zpart += __shfl_xor_sync(0xffffffffu, zpart, 1);
    zpart += __shfl_xor_sync(0xffffffffu, zpart, 2);
    if (jg == 0) z_s[m] = zpart;
    __syncthreads();

    // epilogue: divide by Z, ELU, store
    #pragma unroll
    for (int rr = 0; rr < 8; rr++) {
        const float inv = 1.0f / z_s[r0 + rr];
        float4 o;
        float v;
        v = acc[rr][0] * inv; o.x = v > 0.f ? v : expm1f(v);
        v = acc[rr][1] * inv; o.y = v > 0.f ? v : expm1f(v);
        v = acc[rr][2] * inv; o.z = v > 0.f ? v : expm1f(v);
        v = acc[rr][3] * inv; o.w = v > 0.f ? v : expm1f(v);
        *(float4*)(out + (size_t)(row0 + r0 + rr) * FOUT + f0) = o;
    }
}

// ============================================================
extern "C" void kernel_launch(void* const* d_in, const int* in_sizes, int n_in,
                              void* d_out, int out_size) {
    const float* h   = (const float*)d_in[0];
    const int*   adj = (const int*)d_in[1];
    const float* W   = (const float*)d_in[2];
    const float* a1  = (const float*)d_in[3];
    const float* a2  = (const float*)d_in[4];
    float* out = (float*)d_out;

    k_wh     <<<N / 32, 128>>>(h, W);
    k_s12    <<<N / 8, 256>>>(a1, a2);
    k_max    <<<1, 256>>>();
    k_factors<<<N / 256, 256>>>();
    k_attn   <<<N / MT, 256>>>(adj, out);
}